// round 1
// baseline (speedup 1.0000x reference)
#include <cuda_runtime.h>
#include <math.h>

// ============================================================================
// PermInvariantQNN — exact piecewise-linear collapse of the scalar encoder.
//
// encoder: per scalar x: h1 = relu(a*x+b1) (20), h2 = relu(W2^T h1 + b2) (20),
//          moments = W3^T h2 + b3 (5).  This is piecewise-linear in x with
//          <= 20 + 21*20 = 440 breakpoints.  Precompute per-segment
//          (slope[5], intercept[5]); then each of the 131072*64 evaluations
//          is a table lookup + 5 FMAs instead of 520 MACs.
// ============================================================================

#define NBP_MAX   512          // >= 440 breakpoints (pad with +INF)
#define NSEG_MAX  512          // >= 441 segments
#define NCELL     4096
#define XLO_F     (-6.0f)
#define STEP_F    (12.0f / 4096.0f)
#define INVSTEP_F (4096.0f / 12.0f)

__device__ float          g_bp[NBP_MAX];
__device__ float          g_seg[NSEG_MAX * 12];   // [s0..s4, c0..c4, pad, pad] per segment
__device__ int            g_nbp;
__device__ unsigned short g_cell[NCELL];          // cell -> #breakpoints <= cell left edge

// ----------------------------------------------------------------------------
// Prep kernel: one block, 512 threads. Builds the PWL table each launch.
// ----------------------------------------------------------------------------
__global__ void prep_kernel(const float* __restrict__ eW1, const float* __restrict__ eb1,
                            const float* __restrict__ eW2, const float* __restrict__ eb2,
                            const float* __restrict__ eW3, const float* __restrict__ eb3)
{
    __shared__ float sa[20], sb1[20], sW2[400], sb2[20], sW3[100], sb3[5];
    __shared__ float s_t[21];
    __shared__ int   s_n1;
    __shared__ float cand[512];
    __shared__ float sorted_bp[512];
    __shared__ int   s_n;

    const int tid = threadIdx.x;

    if (tid < 20)  { sa[tid] = eW1[tid]; sb1[tid] = eb1[tid]; sb2[tid] = eb2[tid]; }
    if (tid < 400) sW2[tid] = eW2[tid];
    if (tid < 100) sW3[tid] = eW3[tid];
    if (tid < 5)   sb3[tid] = eb3[tid];
    cand[tid] = INFINITY;
    if (tid == 0) s_n = 0;
    __syncthreads();

    // ---- layer-1 breakpoints t_j = -b1_j / a_j, sorted (tiny: one thread) ----
    if (tid == 0) {
        float t[20]; int n1 = 0;
        for (int j = 0; j < 20; j++) {
            float a = sa[j];
            if (a != 0.0f) {
                float tj = -sb1[j] / a;
                if (isfinite(tj)) t[n1++] = tj;
            }
        }
        for (int i = 1; i < n1; i++) {           // insertion sort
            float v = t[i]; int j = i - 1;
            while (j >= 0 && t[j] > v) { t[j + 1] = t[j]; j--; }
            t[j + 1] = v;
        }
        for (int i = 0; i < n1; i++) { s_t[i] = t[i]; cand[i] = t[i]; }
        s_n1 = n1;
    }
    __syncthreads();
    const int n1 = s_n1;

    // ---- layer-2 zero crossings: one thread per (layer1-segment p, unit k) ----
    if (tid < 21 * 20) {
        int p = tid / 20, k = tid % 20;
        if (p <= n1) {
            float lo = (p == 0)  ? -INFINITY : s_t[p - 1];
            float hi = (p == n1) ?  INFINITY : s_t[p];
            float xr;
            if (n1 == 0)      xr = 0.0f;
            else if (p == 0)  xr = s_t[0] - 1.0f;
            else if (p == n1) xr = s_t[n1 - 1] + 1.0f;
            else              xr = 0.5f * (lo + hi);
            float zs = 0.0f, zi = sb2[k];
            for (int j = 0; j < 20; j++) {
                float pre = fmaf(sa[j], xr, sb1[j]);
                if (pre > 0.0f) {
                    zs = fmaf(sa[j],  sW2[j * 20 + k], zs);
                    zi = fmaf(sb1[j], sW2[j * 20 + k], zi);
                }
            }
            if (zs != 0.0f) {
                float xc = -zi / zs;
                if (isfinite(xc) && xc > lo && xc < hi)
                    cand[20 + p * 20 + k] = xc;
            }
        }
    }
    __syncthreads();

    // ---- rank sort (512 elements, broadcast scan, single barrier) ----
    {
        float v = cand[tid];
        int r = 0;
        for (int j = 0; j < 512; j++) {
            float u = cand[j];
            r += (u < v) || (u == v && j < tid);
        }
        sorted_bp[r] = v;
        if (isfinite(v)) atomicAdd(&s_n, 1);
    }
    __syncthreads();
    const int n = s_n;
    if (tid == 0) g_nbp = n;
    if (tid < n)  g_bp[tid] = sorted_bp[tid];

    // ---- per-segment analytic slope/intercept (thread i -> segment i) ----
    if (tid <= n) {
        float xr;
        if (n == 0)       xr = 0.0f;
        else if (tid == 0) xr = sorted_bp[0] - 1.0f;
        else if (tid == n) xr = sorted_bp[n - 1] + 1.0f;
        else               xr = 0.5f * (sorted_bp[tid - 1] + sorted_bp[tid]);

        float ha[20], hb[20];
        #pragma unroll
        for (int j = 0; j < 20; j++) {
            float pre = fmaf(sa[j], xr, sb1[j]);
            bool act = pre > 0.0f;
            ha[j] = act ? sa[j]  : 0.0f;
            hb[j] = act ? sb1[j] : 0.0f;
        }
        float sm[5] = {0, 0, 0, 0, 0}, cm[5] = {0, 0, 0, 0, 0};
        for (int k = 0; k < 20; k++) {
            float zs = 0.0f, zi = sb2[k];
            #pragma unroll
            for (int j = 0; j < 20; j++) {
                zs = fmaf(ha[j], sW2[j * 20 + k], zs);
                zi = fmaf(hb[j], sW2[j * 20 + k], zi);
            }
            if (fmaf(zs, xr, zi) > 0.0f) {
                #pragma unroll
                for (int m = 0; m < 5; m++) {
                    sm[m] = fmaf(zs, sW3[k * 5 + m], sm[m]);
                    cm[m] = fmaf(zi, sW3[k * 5 + m], cm[m]);
                }
            }
        }
        #pragma unroll
        for (int m = 0; m < 5; m++) {
            g_seg[tid * 12 + m]     = sm[m];
            g_seg[tid * 12 + 5 + m] = cm[m] + sb3[m];
        }
        g_seg[tid * 12 + 10] = 0.0f;
        g_seg[tid * 12 + 11] = 0.0f;
    }

    // ---- grid accelerator: cell -> #breakpoints <= cell left edge ----
    for (int c = tid; c < NCELL; c += 512) {
        float left = XLO_F + (float)c * STEP_F;
        int lo = 0, hi = n;
        while (lo < hi) {
            int mid = (lo + hi) >> 1;
            if (sorted_bp[mid] <= left) lo = mid + 1; else hi = mid;
        }
        g_cell[c] = (unsigned short)lo;
    }
}

// ----------------------------------------------------------------------------
// Main kernel
// ----------------------------------------------------------------------------
__device__ __forceinline__ void pwl_eval(float x, int n,
                                         const float* s_bp,
                                         const unsigned short* s_cell,
                                         const float* s_seg,
                                         float* acc)
{
    float fc = (x - XLO_F) * INVSTEP_F;
    int s;
    if (fc >= 0.0f && fc < (float)NCELL) s = s_cell[(int)fc];
    else                                 s = (fc < 0.0f) ? 0 : n;
    // fixups handle any grid rounding + out-of-grid tails (x ~ N(0,1))
    while (s > 0 && s_bp[s - 1] > x) --s;
    while (s < n && s_bp[s] <= x)    ++s;

    const float* sg = s_seg + s * 12;
    float4 A  = *(const float4*)(sg);      // s0 s1 s2 s3
    float4 Bv = *(const float4*)(sg + 4);  // s4 c0 c1 c2
    float4 C  = *(const float4*)(sg + 8);  // c3 c4 -  -
    acc[0] += fmaf(A.x,  x, Bv.y);
    acc[1] += fmaf(A.y,  x, Bv.z);
    acc[2] += fmaf(A.z,  x, Bv.w);
    acc[3] += fmaf(A.w,  x, C.x);
    acc[4] += fmaf(Bv.x, x, C.y);
}

__global__ __launch_bounds__(256, 2) void main_kernel(
    const float* __restrict__ inv,  const float* __restrict__ noninv,
    const float* __restrict__ dW1,  const float* __restrict__ db1,
    const float* __restrict__ dW2,  const float* __restrict__ db2,
    const float* __restrict__ dW3,  const float* __restrict__ db3,
    float* __restrict__ out)
{
    __shared__ __align__(16) float s_bp[NBP_MAX];
    __shared__ __align__(16) float s_seg[NSEG_MAX * 12];
    __shared__ unsigned short     s_cell[NCELL];
    __shared__ float              s_dw[784];   // dW1[260] db1[20] dW2[400] db2[20] dW3[80] db3[4]
    __shared__ int                s_nsh;

    const int tid = threadIdx.x;

    if (tid == 0) s_nsh = g_nbp;
    s_bp[tid]       = g_bp[tid];
    s_bp[tid + 256] = g_bp[tid + 256];
    for (int i = tid; i < NSEG_MAX * 12; i += 256) s_seg[i]  = g_seg[i];
    for (int i = tid; i < NCELL;         i += 256) s_cell[i] = g_cell[i];
    for (int i = tid; i < 260; i += 256) s_dw[i] = dW1[i];
    if (tid < 20) s_dw[260 + tid] = db1[tid];
    for (int i = tid; i < 400; i += 256) s_dw[280 + i] = dW2[i];
    if (tid < 20) s_dw[680 + tid] = db2[tid];
    if (tid < 80) s_dw[700 + tid] = dW3[tid];
    if (tid < 4)  s_dw[780 + tid] = db3[tid];
    __syncthreads();

    const int n  = s_nsh;
    const int r0 = blockIdx.x * 512 + tid;   // 256 blocks x 512 rows
    const int r1 = r0 + 256;

    // -------- encoder: 64 PWL evals per row, accumulated --------
    float acc0[5] = {0, 0, 0, 0, 0};
    float acc1[5] = {0, 0, 0, 0, 0};
    const float4* p0 = (const float4*)inv + (size_t)r0 * 16;
    const float4* p1 = (const float4*)inv + (size_t)r1 * 16;
    #pragma unroll 4
    for (int i = 0; i < 16; i++) {
        float4 a = p0[i];
        float4 b = p1[i];
        pwl_eval(a.x, n, s_bp, s_cell, s_seg, acc0);
        pwl_eval(a.y, n, s_bp, s_cell, s_seg, acc0);
        pwl_eval(a.z, n, s_bp, s_cell, s_seg, acc0);
        pwl_eval(a.w, n, s_bp, s_cell, s_seg, acc0);
        pwl_eval(b.x, n, s_bp, s_cell, s_seg, acc1);
        pwl_eval(b.y, n, s_bp, s_cell, s_seg, acc1);
        pwl_eval(b.z, n, s_bp, s_cell, s_seg, acc1);
        pwl_eval(b.w, n, s_bp, s_cell, s_seg, acc1);
    }

    // -------- decoder: 13 -> 20 -> 20 -> 4, two rows share weight loads --------
    float cat0[13], cat1[13];
    #pragma unroll
    for (int m = 0; m < 5; m++) {
        cat0[m] = acc0[m] * (1.0f / 64.0f);
        cat1[m] = acc1[m] * (1.0f / 64.0f);
    }
    {
        float4 u0 = *(const float4*)(noninv + (size_t)r0 * 8);
        float4 u1 = *(const float4*)(noninv + (size_t)r0 * 8 + 4);
        cat0[5] = u0.x; cat0[6] = u0.y; cat0[7]  = u0.z; cat0[8]  = u0.w;
        cat0[9] = u1.x; cat0[10] = u1.y; cat0[11] = u1.z; cat0[12] = u1.w;
        float4 v0 = *(const float4*)(noninv + (size_t)r1 * 8);
        float4 v1 = *(const float4*)(noninv + (size_t)r1 * 8 + 4);
        cat1[5] = v0.x; cat1[6] = v0.y; cat1[7]  = v0.z; cat1[8]  = v0.w;
        cat1[9] = v1.x; cat1[10] = v1.y; cat1[11] = v1.z; cat1[12] = v1.w;
    }

    float h0[20], h1[20];
    #pragma unroll
    for (int k = 0; k < 20; k++) {
        float z0 = s_dw[260 + k], z1 = z0;
        #pragma unroll
        for (int c = 0; c < 13; c++) {
            float w = s_dw[c * 20 + k];
            z0 = fmaf(cat0[c], w, z0);
            z1 = fmaf(cat1[c], w, z1);
        }
        h0[k] = fmaxf(z0, 0.0f);
        h1[k] = fmaxf(z1, 0.0f);
    }

    float g0[20], g1[20];
    #pragma unroll
    for (int k = 0; k < 20; k++) {
        float z0 = s_dw[680 + k], z1 = z0;
        #pragma unroll
        for (int j = 0; j < 20; j++) {
            float w = s_dw[280 + j * 20 + k];
            z0 = fmaf(h0[j], w, z0);
            z1 = fmaf(h1[j], w, z1);
        }
        g0[k] = fmaxf(z0, 0.0f);
        g1[k] = fmaxf(z1, 0.0f);
    }

    float o0[4], o1[4];
    #pragma unroll
    for (int m = 0; m < 4; m++) {
        float z0 = s_dw[780 + m], z1 = z0;
        #pragma unroll
        for (int k = 0; k < 20; k++) {
            float w = s_dw[700 + k * 4 + m];
            z0 = fmaf(g0[k], w, z0);
            z1 = fmaf(g1[k], w, z1);
        }
        o0[m] = z0; o1[m] = z1;
    }
    *(float4*)(out + (size_t)r0 * 4) = make_float4(o0[0], o0[1], o0[2], o0[3]);
    *(float4*)(out + (size_t)r1 * 4) = make_float4(o1[0], o1[1], o1[2], o1[3]);
}

// ----------------------------------------------------------------------------
extern "C" void kernel_launch(void* const* d_in, const int* in_sizes, int n_in,
                              void* d_out, int out_size)
{
    (void)in_sizes; (void)n_in; (void)out_size;
    const float* invar  = (const float*)d_in[0];
    const float* noninv = (const float*)d_in[1];
    const float* eW1 = (const float*)d_in[2];
    const float* eb1 = (const float*)d_in[3];
    const float* eW2 = (const float*)d_in[4];
    const float* eb2 = (const float*)d_in[5];
    const float* eW3 = (const float*)d_in[6];
    const float* eb3 = (const float*)d_in[7];
    const float* dW1 = (const float*)d_in[8];
    const float* db1 = (const float*)d_in[9];
    const float* dW2 = (const float*)d_in[10];
    const float* db2 = (const float*)d_in[11];
    const float* dW3 = (const float*)d_in[12];
    const float* db3 = (const float*)d_in[13];

    prep_kernel<<<1, 512>>>(eW1, eb1, eW2, eb2, eW3, eb3);
    main_kernel<<<256, 256>>>(invar, noninv, dW1, db1, dW2, db2, dW3, db3,
                              (float*)d_out);
}

// round 2
// speedup vs baseline: 1.0504x; 1.0504x over previous
#include <cuda_runtime.h>
#include <cuda_fp16.h>
#include <math.h>

// ============================================================================
// PermInvariantQNN — exact piecewise-linear collapse of the scalar encoder.
// Round 2: fp16 mid-centered segment records (24B), split parallel prep,
//          1 row/thread for occupancy, vectorized decoder weight loads.
// ============================================================================

#define NBP_MAX   512
#define NSEG_MAX  512
#define NCELL     4096
#define XLO_F     (-6.0f)
#define STEP_F    (12.0f / 4096.0f)
#define INVSTEP_F (4096.0f / 12.0f)

// record: 6 words per segment: [xmid(f32), h2(s0,v0), h2(s1,v1), h2(s2,v2),
//                               h2(s3,v3), h2(s4,v4)]
__device__ float          g_bp[NBP_MAX];        // sorted breakpoints, +INF padded
__device__ unsigned int   g_rec[NSEG_MAX * 6];
__device__ int            g_nbp;
__device__ unsigned short g_cell[NCELL];        // cell -> #breakpoints <= cell left edge

// ----------------------------------------------------------------------------
// Prep A: 1 block, 512 threads. Candidates + sort + grid table. (cheap part)
// ----------------------------------------------------------------------------
__global__ void prep_sort_kernel(const float* __restrict__ eW1, const float* __restrict__ eb1,
                                 const float* __restrict__ eW2, const float* __restrict__ eb2)
{
    __shared__ float sa[20], sb1[20], sW2[400], sb2[20];
    __shared__ float s_t[21];
    __shared__ int   s_n1;
    __shared__ float cand[512];
    __shared__ float sorted_bp[512];
    __shared__ int   s_n;

    const int tid = threadIdx.x;

    if (tid < 20)  { sa[tid] = eW1[tid]; sb1[tid] = eb1[tid]; sb2[tid] = eb2[tid]; }
    if (tid < 400) sW2[tid] = eW2[tid];
    cand[tid] = INFINITY;
    if (tid == 0) s_n = 0;
    __syncthreads();

    // layer-1 breakpoints (tiny, one thread)
    if (tid == 0) {
        float t[20]; int n1 = 0;
        for (int j = 0; j < 20; j++) {
            float a = sa[j];
            if (a != 0.0f) {
                float tj = -sb1[j] / a;
                if (isfinite(tj)) t[n1++] = tj;
            }
        }
        for (int i = 1; i < n1; i++) {
            float v = t[i]; int j = i - 1;
            while (j >= 0 && t[j] > v) { t[j + 1] = t[j]; j--; }
            t[j + 1] = v;
        }
        for (int i = 0; i < n1; i++) { s_t[i] = t[i]; cand[i] = t[i]; }
        s_n1 = n1;
    }
    __syncthreads();
    const int n1 = s_n1;

    // layer-2 zero crossings: one thread per (layer1-segment p, unit k)
    if (tid < 21 * 20) {
        int p = tid / 20, k = tid % 20;
        if (p <= n1) {
            float lo = (p == 0)  ? -INFINITY : s_t[p - 1];
            float hi = (p == n1) ?  INFINITY : s_t[p];
            float xr;
            if (n1 == 0)      xr = 0.0f;
            else if (p == 0)  xr = s_t[0] - 1.0f;
            else if (p == n1) xr = s_t[n1 - 1] + 1.0f;
            else              xr = 0.5f * (lo + hi);
            float zs = 0.0f, zi = sb2[k];
            for (int j = 0; j < 20; j++) {
                float pre = fmaf(sa[j], xr, sb1[j]);
                if (pre > 0.0f) {
                    zs = fmaf(sa[j],  sW2[j * 20 + k], zs);
                    zi = fmaf(sb1[j], sW2[j * 20 + k], zi);
                }
            }
            if (zs != 0.0f) {
                float xc = -zi / zs;
                if (isfinite(xc) && xc > lo && xc < hi)
                    cand[20 + p * 20 + k] = xc;
            }
        }
    }
    __syncthreads();

    // rank sort (broadcast scan, single barrier)
    {
        float v = cand[tid];
        int r = 0;
        for (int j = 0; j < 512; j++) {
            float u = cand[j];
            r += (u < v) || (u == v && j < tid);
        }
        sorted_bp[r] = v;
        if (isfinite(v)) atomicAdd(&s_n, 1);
    }
    __syncthreads();
    const int n = s_n;
    if (tid == 0) g_nbp = n;
    g_bp[tid] = sorted_bp[tid];   // +INF padded beyond n

    // grid accelerator
    for (int c = tid; c < NCELL; c += 512) {
        float left = XLO_F + (float)c * STEP_F;
        int lo = 0, hi = n;
        while (lo < hi) {
            int mid = (lo + hi) >> 1;
            if (sorted_bp[mid] <= left) lo = mid + 1; else hi = mid;
        }
        g_cell[c] = (unsigned short)lo;
    }
}

// ----------------------------------------------------------------------------
// Prep B: 2 blocks x 256 threads. Per-segment slopes/values, fp16 packing.
// ----------------------------------------------------------------------------
__global__ void prep_seg_kernel(const float* __restrict__ eW1, const float* __restrict__ eb1,
                                const float* __restrict__ eW2, const float* __restrict__ eb2,
                                const float* __restrict__ eW3, const float* __restrict__ eb3)
{
    __shared__ float sa[20], sb1[20], sW2[400], sb2[20], sW3[100], sb3[5];
    const int tid = threadIdx.x;
    if (tid < 20)  { sa[tid] = eW1[tid]; sb1[tid] = eb1[tid]; sb2[tid] = eb2[tid]; }
    if (tid < 400) sW2[tid] = eW2[tid];
    if (tid < 100) sW3[tid] = eW3[tid];
    if (tid < 5)   sb3[tid] = eb3[tid];
    __syncthreads();

    const int sid = blockIdx.x * 256 + tid;
    const int n   = g_nbp;
    if (sid > n) return;

    float xr;
    if (n == 0)        xr = 0.0f;
    else if (sid == 0) xr = g_bp[0] - 1.0f;
    else if (sid == n) xr = g_bp[n - 1] + 1.0f;
    else               xr = 0.5f * (g_bp[sid - 1] + g_bp[sid]);

    float ha[20], hb[20];
    #pragma unroll
    for (int j = 0; j < 20; j++) {
        float pre = fmaf(sa[j], xr, sb1[j]);
        bool act = pre > 0.0f;
        ha[j] = act ? sa[j]  : 0.0f;
        hb[j] = act ? sb1[j] : 0.0f;
    }
    float sm[5] = {0, 0, 0, 0, 0}, cm[5] = {0, 0, 0, 0, 0};
    for (int k = 0; k < 20; k++) {
        float zs = 0.0f, zi = sb2[k];
        #pragma unroll
        for (int j = 0; j < 20; j++) {
            zs = fmaf(ha[j], sW2[j * 20 + k], zs);
            zi = fmaf(hb[j], sW2[j * 20 + k], zi);
        }
        if (fmaf(zs, xr, zi) > 0.0f) {
            #pragma unroll
            for (int m = 0; m < 5; m++) {
                sm[m] = fmaf(zs, sW3[k * 5 + m], sm[m]);
                cm[m] = fmaf(zi, sW3[k * 5 + m], cm[m]);
            }
        }
    }
    unsigned int* rec = g_rec + sid * 6;
    rec[0] = __float_as_uint(xr);
    #pragma unroll
    for (int m = 0; m < 5; m++) {
        float v = fmaf(sm[m], xr, cm[m] + sb3[m]);   // f_m at xr, fp32
        __half2 h = __floats2half2_rn(sm[m], v);
        rec[1 + m] = *(unsigned int*)&h;
    }
}

// ----------------------------------------------------------------------------
// Main kernel: 1 row per thread.
// ----------------------------------------------------------------------------
__device__ __forceinline__ void pwl_eval(float x,
                                         const float* __restrict__ s_bp,
                                         const unsigned short* __restrict__ s_cell,
                                         const uint2* __restrict__ s_rec,
                                         float acc[5])
{
    float fc = fmaf(x, INVSTEP_F, -XLO_F * INVSTEP_F);
    int c = __float2int_rz(fc);
    c = min(max(c, 0), NCELL - 1);
    int s = s_cell[c];
    while (s > 0 && s_bp[s - 1] > x) --s;   // cold: only fp-rounding / x < XLO
    while (s_bp[s] <= x) ++s;               // avg ~0.1 iters; +INF padding stops it

    const uint2* p = s_rec + s * 3;         // 24B record = 3 x uint2, 8B aligned
    uint2 r0 = p[0];
    uint2 r1 = p[1];
    uint2 r2 = p[2];
    float dx = x - __uint_as_float(r0.x);
    float2 m0 = __half22float2(*(__half2*)&r0.y);
    float2 m1 = __half22float2(*(__half2*)&r1.x);
    float2 m2 = __half22float2(*(__half2*)&r1.y);
    float2 m3 = __half22float2(*(__half2*)&r2.x);
    float2 m4 = __half22float2(*(__half2*)&r2.y);
    acc[0] += fmaf(m0.x, dx, m0.y);
    acc[1] += fmaf(m1.x, dx, m1.y);
    acc[2] += fmaf(m2.x, dx, m2.y);
    acc[3] += fmaf(m3.x, dx, m3.y);
    acc[4] += fmaf(m4.x, dx, m4.y);
}

__global__ __launch_bounds__(256, 3) void main_kernel(
    const float* __restrict__ inv,  const float* __restrict__ noninv,
    const float* __restrict__ dW1,  const float* __restrict__ db1,
    const float* __restrict__ dW2,  const float* __restrict__ db2,
    const float* __restrict__ dW3,  const float* __restrict__ db3,
    float* __restrict__ out)
{
    __shared__ __align__(16) float          s_bp[NBP_MAX];
    __shared__ __align__(16) unsigned int   s_rec[NSEG_MAX * 6];
    __shared__ __align__(16) unsigned short s_cell[NCELL];
    __shared__ __align__(16) float          s_dw[784]; // dW1[260] db1[20] dW2[400] db2[20] dW3[80] db3[4]

    const int tid = threadIdx.x;

    // table loads (vectorized where possible)
    {
        const uint4* src = (const uint4*)g_rec;           // 768 uint4
        uint4* dst = (uint4*)s_rec;
        for (int i = tid; i < NSEG_MAX * 6 / 4; i += 256) dst[i] = src[i];
        const float2* bsrc = (const float2*)g_bp;
        float2* bdst = (float2*)s_bp;
        if (tid < 256) bdst[tid] = bsrc[tid];
        const uint4* csrc = (const uint4*)g_cell;         // 4096 u16 = 512 uint4
        uint4* cdst = (uint4*)s_cell;
        for (int i = tid; i < NCELL / 8; i += 256) cdst[i] = csrc[i];
        for (int i = tid; i < 260; i += 256) s_dw[i] = dW1[i];
        if (tid < 20) s_dw[260 + tid] = db1[tid];
        for (int i = tid; i < 400; i += 256) s_dw[280 + i] = dW2[i];
        if (tid < 20) s_dw[680 + tid] = db2[tid];
        if (tid < 80) s_dw[700 + tid] = dW3[tid];
        if (tid < 4)  s_dw[780 + tid] = db3[tid];
    }
    __syncthreads();

    const int r = blockIdx.x * 256 + tid;

    // -------- encoder: 64 PWL evals --------
    float acc[5] = {0, 0, 0, 0, 0};
    const float4* p0 = (const float4*)inv + (size_t)r * 16;
    #pragma unroll 4
    for (int i = 0; i < 16; i++) {
        float4 a = p0[i];
        pwl_eval(a.x, s_bp, s_cell, (const uint2*)s_rec, acc);
        pwl_eval(a.y, s_bp, s_cell, (const uint2*)s_rec, acc);
        pwl_eval(a.z, s_bp, s_cell, (const uint2*)s_rec, acc);
        pwl_eval(a.w, s_bp, s_cell, (const uint2*)s_rec, acc);
    }

    // -------- decoder: 13 -> 20 -> 20 -> 4 --------
    float cat[13];
    #pragma unroll
    for (int m = 0; m < 5; m++) cat[m] = acc[m] * (1.0f / 64.0f);
    {
        float4 u0 = *(const float4*)(noninv + (size_t)r * 8);
        float4 u1 = *(const float4*)(noninv + (size_t)r * 8 + 4);
        cat[5] = u0.x; cat[6] = u0.y; cat[7]  = u0.z; cat[8]  = u0.w;
        cat[9] = u1.x; cat[10] = u1.y; cat[11] = u1.z; cat[12] = u1.w;
    }

    float h[20];
    #pragma unroll
    for (int kg = 0; kg < 20; kg += 4) {
        float4 z = *(const float4*)&s_dw[260 + kg];       // bias
        #pragma unroll
        for (int c = 0; c < 13; c++) {
            float4 w = *(const float4*)&s_dw[c * 20 + kg];
            z.x = fmaf(cat[c], w.x, z.x);
            z.y = fmaf(cat[c], w.y, z.y);
            z.z = fmaf(cat[c], w.z, z.z);
            z.w = fmaf(cat[c], w.w, z.w);
        }
        h[kg] = fmaxf(z.x, 0.0f); h[kg + 1] = fmaxf(z.y, 0.0f);
        h[kg + 2] = fmaxf(z.z, 0.0f); h[kg + 3] = fmaxf(z.w, 0.0f);
    }

    float g[20];
    #pragma unroll
    for (int kg = 0; kg < 20; kg += 4) {
        float4 z = *(const float4*)&s_dw[680 + kg];
        #pragma unroll
        for (int j = 0; j < 20; j++) {
            float4 w = *(const float4*)&s_dw[280 + j * 20 + kg];
            z.x = fmaf(h[j], w.x, z.x);
            z.y = fmaf(h[j], w.y, z.y);
            z.z = fmaf(h[j], w.z, z.z);
            z.w = fmaf(h[j], w.w, z.w);
        }
        g[kg] = fmaxf(z.x, 0.0f); g[kg + 1] = fmaxf(z.y, 0.0f);
        g[kg + 2] = fmaxf(z.z, 0.0f); g[kg + 3] = fmaxf(z.w, 0.0f);
    }

    float4 o = *(const float4*)&s_dw[780];
    #pragma unroll
    for (int k = 0; k < 20; k++) {
        float4 w = *(const float4*)&s_dw[700 + k * 4];
        o.x = fmaf(g[k], w.x, o.x);
        o.y = fmaf(g[k], w.y, o.y);
        o.z = fmaf(g[k], w.z, o.z);
        o.w = fmaf(g[k], w.w, o.w);
    }
    *(float4*)(out + (size_t)r * 4) = o;
}

// ----------------------------------------------------------------------------
extern "C" void kernel_launch(void* const* d_in, const int* in_sizes, int n_in,
                              void* d_out, int out_size)
{
    (void)in_sizes; (void)n_in; (void)out_size;
    const float* invar  = (const float*)d_in[0];
    const float* noninv = (const float*)d_in[1];
    const float* eW1 = (const float*)d_in[2];
    const float* eb1 = (const float*)d_in[3];
    const float* eW2 = (const float*)d_in[4];
    const float* eb2 = (const float*)d_in[5];
    const float* eW3 = (const float*)d_in[6];
    const float* eb3 = (const float*)d_in[7];
    const float* dW1 = (const float*)d_in[8];
    const float* db1 = (const float*)d_in[9];
    const float* dW2 = (const float*)d_in[10];
    const float* db2 = (const float*)d_in[11];
    const float* dW3 = (const float*)d_in[12];
    const float* db3 = (const float*)d_in[13];

    prep_sort_kernel<<<1, 512>>>(eW1, eb1, eW2, eb2);
    prep_seg_kernel<<<2, 256>>>(eW1, eb1, eW2, eb2, eW3, eb3);
    main_kernel<<<512, 256>>>(invar, noninv, dW1, db1, dW2, db2, dW3, db3,
                              (float*)d_out);
}

// round 3
// speedup vs baseline: 1.3032x; 1.2406x over previous
#include <cuda_runtime.h>
#include <cuda_fp16.h>
#include <math.h>

// ============================================================================
// PermInvariantQNN — exact piecewise-linear collapse of the scalar encoder.
// Round 3: fused parallel prep (bitonic sort + scatter grid), MLP-batched
//          PWL evaluation in main, launch_bounds(256,2) to avoid spills.
// ============================================================================

#define NBP_MAX   512
#define NSEG_MAX  512
#define NCELL     4096
#define XLO_F     (-6.0f)
#define XHI_F     (6.0f)
#define STEP_F    (12.0f / 4096.0f)
#define INVSTEP_F (4096.0f / 12.0f)

// record: 6 words/segment: [xmid(f32), h2(s0,v0)..h2(s4,v4)]
__device__ float          g_bp[NBP_MAX];        // sorted breakpoints, +INF padded
__device__ unsigned int   g_rec[NSEG_MAX * 6];
__device__ int            g_nbp;
__device__ unsigned short g_cell[NCELL];        // cell -> #breakpoints <= cell left edge

// ----------------------------------------------------------------------------
// Fused prep: 1 block x 512 threads.
// ----------------------------------------------------------------------------
__global__ void prep_kernel(const float* __restrict__ eW1, const float* __restrict__ eb1,
                            const float* __restrict__ eW2, const float* __restrict__ eb2,
                            const float* __restrict__ eW3, const float* __restrict__ eb3)
{
    __shared__ float sa[20], sb1[20], sW2[400], sb2[20], sW3[100], sb3[5];
    __shared__ float s_t[21];
    __shared__ int   s_n1;
    __shared__ float cand[512];
    __shared__ int   s_n;

    const int tid = threadIdx.x;

    if (tid < 20)  { sa[tid] = eW1[tid]; sb1[tid] = eb1[tid]; sb2[tid] = eb2[tid]; }
    if (tid < 400) sW2[tid] = eW2[tid];
    if (tid < 100) sW3[tid] = eW3[tid];
    if (tid < 5)   sb3[tid] = eb3[tid];
    cand[tid] = INFINITY;
    if (tid == 0) s_n = 0;
    __syncthreads();

    // ---- phase 1: layer-1 breakpoints, warp-parallel rank sort over 32 ----
    if (tid < 32) {
        float tj = INFINITY;
        if (tid < 20) {
            float a = sa[tid];
            if (a != 0.0f) {
                float t = -sb1[tid] / a;
                if (isfinite(t)) tj = t;
            }
        }
        int rnk = 0;
        #pragma unroll
        for (int j = 0; j < 32; j++) {
            float u = __shfl_sync(0xFFFFFFFFu, tj, j);
            rnk += (u < tj) || (u == tj && j < tid);
        }
        bool fin = isfinite(tj);
        if (fin) { s_t[rnk] = tj; cand[rnk] = tj; }
        unsigned m = __ballot_sync(0xFFFFFFFFu, fin);
        if (tid == 0) { s_n1 = __popc(m); atomicAdd(&s_n, __popc(m)); }
    }
    __syncthreads();
    const int n1 = s_n1;

    // ---- phase 2: layer-2 zero crossings, one thread per (segment p, unit k) ----
    if (tid < 21 * 20) {
        int p = tid / 20, k = tid % 20;
        if (p <= n1) {
            float lo = (p == 0)  ? -INFINITY : s_t[p - 1];
            float hi = (p == n1) ?  INFINITY : s_t[p];
            float xr;
            if (n1 == 0)      xr = 0.0f;
            else if (p == 0)  xr = s_t[0] - 1.0f;
            else if (p == n1) xr = s_t[n1 - 1] + 1.0f;
            else              xr = 0.5f * (lo + hi);
            float zs = 0.0f, zi = sb2[k];
            for (int j = 0; j < 20; j++) {
                float pre = fmaf(sa[j], xr, sb1[j]);
                if (pre > 0.0f) {
                    zs = fmaf(sa[j],  sW2[j * 20 + k], zs);
                    zi = fmaf(sb1[j], sW2[j * 20 + k], zi);
                }
            }
            if (zs != 0.0f) {
                float xc = -zi / zs;
                if (isfinite(xc) && xc > lo && xc < hi) {
                    cand[20 + p * 20 + k] = xc;
                    atomicAdd(&s_n, 1);
                }
            }
        }
    }
    __syncthreads();

    // ---- phase 3: bitonic sort of cand[512] (equal keys fine) ----
    for (int k = 2; k <= 512; k <<= 1) {
        for (int j = k >> 1; j > 0; j >>= 1) {
            int ixj = tid ^ j;
            if (ixj > tid) {
                float a = cand[tid], b = cand[ixj];
                bool dir = ((tid & k) == 0);      // ascending if true
                if ((a > b) == dir) { cand[tid] = b; cand[ixj] = a; }
            }
            __syncthreads();
        }
    }

    const int n = s_n;
    if (tid == 0) g_nbp = n;
    g_bp[tid] = cand[tid];                        // +INF padded beyond n

    // ---- phase 4: grid table via range scatter ----
    // cell[c] = #bp <= left_c.  Thread t writes value t to [A_t, A_{t+1}),
    // A_t = smallest c with left_c >= bp[t-1].
    if (tid <= n) {
        auto cmin = [&](float b) -> int {
            if (!(b > XLO_F)) return 0;
            if (b >= XHI_F)   return NCELL;
            int c = (int)ceilf((b - XLO_F) * INVSTEP_F);
            c = min(max(c, 0), NCELL);
            while (c > 0 && XLO_F + (float)(c - 1) * STEP_F >= b) c--;
            while (c < NCELL && XLO_F + (float)c * STEP_F < b)    c++;
            return c;
        };
        int start = (tid == 0) ? 0     : cmin(cand[tid - 1]);
        int end   = (tid == n) ? NCELL : cmin(cand[tid]);
        for (int c = start; c < end; c++) g_cell[c] = (unsigned short)tid;
    }

    // ---- phase 5: per-segment records (threads 0..n) ----
    if (tid <= n) {
        float xr;
        if (n == 0)        xr = 0.0f;
        else if (tid == 0) xr = cand[0] - 1.0f;
        else if (tid == n) xr = cand[n - 1] + 1.0f;
        else               xr = 0.5f * (cand[tid - 1] + cand[tid]);

        float ha[20], hb[20];
        #pragma unroll
        for (int j = 0; j < 20; j++) {
            float pre = fmaf(sa[j], xr, sb1[j]);
            bool act = pre > 0.0f;
            ha[j] = act ? sa[j]  : 0.0f;
            hb[j] = act ? sb1[j] : 0.0f;
        }
        float sm[5] = {0, 0, 0, 0, 0}, cm[5] = {0, 0, 0, 0, 0};
        for (int k = 0; k < 20; k++) {
            float zs = 0.0f, zi = sb2[k];
            #pragma unroll
            for (int j = 0; j < 20; j++) {
                zs = fmaf(ha[j], sW2[j * 20 + k], zs);
                zi = fmaf(hb[j], sW2[j * 20 + k], zi);
            }
            if (fmaf(zs, xr, zi) > 0.0f) {
                #pragma unroll
                for (int m = 0; m < 5; m++) {
                    sm[m] = fmaf(zs, sW3[k * 5 + m], sm[m]);
                    cm[m] = fmaf(zi, sW3[k * 5 + m], cm[m]);
                }
            }
        }
        unsigned int* rec = g_rec + tid * 6;
        rec[0] = __float_as_uint(xr);
        #pragma unroll
        for (int m = 0; m < 5; m++) {
            float v = fmaf(sm[m], xr, cm[m] + sb3[m]);   // f_m at xr (fp32)
            __half2 h = __floats2half2_rn(sm[m], v);
            rec[1 + m] = *(unsigned int*)&h;
        }
    }
}

// ----------------------------------------------------------------------------
// Main kernel: 1 row/thread; PWL evals batched x4 for smem MLP.
// ----------------------------------------------------------------------------
__device__ __forceinline__ int pwl_find(float x,
                                        const float* __restrict__ s_bp,
                                        const unsigned short* __restrict__ s_cell)
{
    float fc = fmaf(x, INVSTEP_F, 2048.0f);      // (x - XLO)/STEP
    int c = __float2int_rz(fc);
    c = min(max(c, 0), NCELL - 1);
    int s = s_cell[c];
    while (s > 0 && s_bp[s - 1] > x) --s;        // cold
    while (s_bp[s] <= x) ++s;                    // avg ~0.05 iters (+INF stops)
    return s;
}

__device__ __forceinline__ void pwl_acc(float x, const uint2* __restrict__ p,
                                        float acc[5])
{
    uint2 r0 = p[0], r1 = p[1], r2 = p[2];
    float dx = x - __uint_as_float(r0.x);
    float2 m0 = __half22float2(*(__half2*)&r0.y);
    float2 m1 = __half22float2(*(__half2*)&r1.x);
    float2 m2 = __half22float2(*(__half2*)&r1.y);
    float2 m3 = __half22float2(*(__half2*)&r2.x);
    float2 m4 = __half22float2(*(__half2*)&r2.y);
    acc[0] += fmaf(m0.x, dx, m0.y);
    acc[1] += fmaf(m1.x, dx, m1.y);
    acc[2] += fmaf(m2.x, dx, m2.y);
    acc[3] += fmaf(m3.x, dx, m3.y);
    acc[4] += fmaf(m4.x, dx, m4.y);
}

__global__ __launch_bounds__(256, 2) void main_kernel(
    const float* __restrict__ inv,  const float* __restrict__ noninv,
    const float* __restrict__ dW1,  const float* __restrict__ db1,
    const float* __restrict__ dW2,  const float* __restrict__ db2,
    const float* __restrict__ dW3,  const float* __restrict__ db3,
    float* __restrict__ out)
{
    __shared__ __align__(16) float          s_bp[NBP_MAX];
    __shared__ __align__(16) unsigned int   s_rec[NSEG_MAX * 6];
    __shared__ __align__(16) unsigned short s_cell[NCELL];
    __shared__ __align__(16) float          s_dw[784];

    const int tid = threadIdx.x;

    {
        const uint4* src = (const uint4*)g_rec;
        uint4* dst = (uint4*)s_rec;
        for (int i = tid; i < NSEG_MAX * 6 / 4; i += 256) dst[i] = src[i];
        ((float2*)s_bp)[tid] = ((const float2*)g_bp)[tid];
        const uint4* csrc = (const uint4*)g_cell;
        uint4* cdst = (uint4*)s_cell;
        for (int i = tid; i < NCELL / 8; i += 256) cdst[i] = csrc[i];
        for (int i = tid; i < 260; i += 256) s_dw[i] = dW1[i];
        if (tid < 20) s_dw[260 + tid] = db1[tid];
        for (int i = tid; i < 400; i += 256) s_dw[280 + i] = dW2[i];
        if (tid < 20) s_dw[680 + tid] = db2[tid];
        if (tid < 80) s_dw[700 + tid] = dW3[tid];
        if (tid < 4)  s_dw[780 + tid] = db3[tid];
    }
    __syncthreads();

    const int r = blockIdx.x * 256 + tid;
    const uint2* rec = (const uint2*)s_rec;

    // -------- encoder: 64 PWL evals, batched 4 at a time --------
    float acc[5] = {0, 0, 0, 0, 0};
    const float4* p0 = (const float4*)inv + (size_t)r * 16;
    #pragma unroll 4
    for (int i = 0; i < 16; i++) {
        float4 a = p0[i];
        // 1) four independent index finds (interleaved by compiler)
        int sA = pwl_find(a.x, s_bp, s_cell);
        int sB = pwl_find(a.y, s_bp, s_cell);
        int sC = pwl_find(a.z, s_bp, s_cell);
        int sD = pwl_find(a.w, s_bp, s_cell);
        // 2) record loads + FMA accumulate (12 LDS.64 in flight)
        pwl_acc(a.x, rec + sA * 3, acc);
        pwl_acc(a.y, rec + sB * 3, acc);
        pwl_acc(a.z, rec + sC * 3, acc);
        pwl_acc(a.w, rec + sD * 3, acc);
    }

    // -------- decoder: 13 -> 20 -> 20 -> 4 --------
    float cat[13];
    #pragma unroll
    for (int m = 0; m < 5; m++) cat[m] = acc[m] * (1.0f / 64.0f);
    {
        float4 u0 = *(const float4*)(noninv + (size_t)r * 8);
        float4 u1 = *(const float4*)(noninv + (size_t)r * 8 + 4);
        cat[5] = u0.x; cat[6] = u0.y; cat[7]  = u0.z; cat[8]  = u0.w;
        cat[9] = u1.x; cat[10] = u1.y; cat[11] = u1.z; cat[12] = u1.w;
    }

    float h[20];
    #pragma unroll
    for (int kg = 0; kg < 20; kg += 4) {
        float4 z = *(const float4*)&s_dw[260 + kg];
        #pragma unroll
        for (int c = 0; c < 13; c++) {
            float4 w = *(const float4*)&s_dw[c * 20 + kg];
            z.x = fmaf(cat[c], w.x, z.x);
            z.y = fmaf(cat[c], w.y, z.y);
            z.z = fmaf(cat[c], w.z, z.z);
            z.w = fmaf(cat[c], w.w, z.w);
        }
        h[kg] = fmaxf(z.x, 0.0f); h[kg + 1] = fmaxf(z.y, 0.0f);
        h[kg + 2] = fmaxf(z.z, 0.0f); h[kg + 3] = fmaxf(z.w, 0.0f);
    }

    float g[20];
    #pragma unroll
    for (int kg = 0; kg < 20; kg += 4) {
        float4 z = *(const float4*)&s_dw[680 + kg];
        #pragma unroll
        for (int j = 0; j < 20; j++) {
            float4 w = *(const float4*)&s_dw[280 + j * 20 + kg];
            z.x = fmaf(h[j], w.x, z.x);
            z.y = fmaf(h[j], w.y, z.y);
            z.z = fmaf(h[j], w.z, z.z);
            z.w = fmaf(h[j], w.w, z.w);
        }
        g[kg] = fmaxf(z.x, 0.0f); g[kg + 1] = fmaxf(z.y, 0.0f);
        g[kg + 2] = fmaxf(z.z, 0.0f); g[kg + 3] = fmaxf(z.w, 0.0f);
    }

    float4 o = *(const float4*)&s_dw[780];
    #pragma unroll
    for (int k = 0; k < 20; k++) {
        float4 w = *(const float4*)&s_dw[700 + k * 4];
        o.x = fmaf(g[k], w.x, o.x);
        o.y = fmaf(g[k], w.y, o.y);
        o.z = fmaf(g[k], w.z, o.z);
        o.w = fmaf(g[k], w.w, o.w);
    }
    *(float4*)(out + (size_t)r * 4) = o;
}

// ----------------------------------------------------------------------------
extern "C" void kernel_launch(void* const* d_in, const int* in_sizes, int n_in,
                              void* d_out, int out_size)
{
    (void)in_sizes; (void)n_in; (void)out_size;
    const float* invar  = (const float*)d_in[0];
    const float* noninv = (const float*)d_in[1];
    const float* eW1 = (const float*)d_in[2];
    const float* eb1 = (const float*)d_in[3];
    const float* eW2 = (const float*)d_in[4];
    const float* eb2 = (const float*)d_in[5];
    const float* eW3 = (const float*)d_in[6];
    const float* eb3 = (const float*)d_in[7];
    const float* dW1 = (const float*)d_in[8];
    const float* db1 = (const float*)d_in[9];
    const float* dW2 = (const float*)d_in[10];
    const float* db2 = (const float*)d_in[11];
    const float* dW3 = (const float*)d_in[12];
    const float* db3 = (const float*)d_in[13];

    prep_kernel<<<1, 512>>>(eW1, eb1, eW2, eb2, eW3, eb3);
    main_kernel<<<512, 256>>>(invar, noninv, dW1, db1, dW2, db2, dW3, db3,
                              (float*)d_out);
}

// round 4
// speedup vs baseline: 1.5702x; 1.2049x over previous
#include <cuda_runtime.h>
#include <cuda_fp16.h>
#include <math.h>

// ============================================================================
// PermInvariantQNN — exact piecewise-linear collapse of the scalar encoder.
// Round 4: split encoder/decoder kernels for occupancy; smaller smem tables;
//          single-probe segment find; 1/64 folded into the PWL table.
// ============================================================================

#define BATCH     131072
#define NBP_MAX   512
#define NSEG_MAX  512
#define NCELL     2048
#define XLO_F     (-6.0f)
#define XHI_F     (6.0f)
#define STEP_F    (12.0f / 2048.0f)
#define INVSTEP_F (2048.0f / 12.0f)
#define HALFCELLS 1024.0f

// record: 6 words/segment: [xmid(f32), h2(s0,v0)..h2(s4,v4)], pre-scaled by 1/64
__device__ float          g_bp[NBP_MAX];        // sorted breakpoints, +INF padded
__device__ unsigned int   g_rec[NSEG_MAX * 6];
__device__ int            g_nbp;
__device__ unsigned short g_cell[NCELL];        // cell -> #breakpoints <= cell left edge
__device__ float          g_mom[5 * BATCH];     // SoA moments scratch

// ----------------------------------------------------------------------------
// Fused prep: 1 block x 512 threads.
// ----------------------------------------------------------------------------
__global__ void prep_kernel(const float* __restrict__ eW1, const float* __restrict__ eb1,
                            const float* __restrict__ eW2, const float* __restrict__ eb2,
                            const float* __restrict__ eW3, const float* __restrict__ eb3)
{
    __shared__ float sa[20], sb1[20], sW2[400], sb2[20], sW3[100], sb3[5];
    __shared__ float s_t[21];
    __shared__ int   s_n1;
    __shared__ float cand[512];
    __shared__ int   s_n;

    const int tid = threadIdx.x;

    if (tid < 20)  { sa[tid] = eW1[tid]; sb1[tid] = eb1[tid]; sb2[tid] = eb2[tid]; }
    if (tid < 400) sW2[tid] = eW2[tid];
    if (tid < 100) sW3[tid] = eW3[tid];
    if (tid < 5)   sb3[tid] = eb3[tid];
    cand[tid] = INFINITY;
    if (tid == 0) s_n = 0;
    __syncthreads();

    // ---- phase 1: layer-1 breakpoints, warp-parallel rank sort over 32 ----
    if (tid < 32) {
        float tj = INFINITY;
        if (tid < 20) {
            float a = sa[tid];
            if (a != 0.0f) {
                float t = -sb1[tid] / a;
                if (isfinite(t)) tj = t;
            }
        }
        int rnk = 0;
        #pragma unroll
        for (int j = 0; j < 32; j++) {
            float u = __shfl_sync(0xFFFFFFFFu, tj, j);
            rnk += (u < tj) || (u == tj && j < tid);
        }
        bool fin = isfinite(tj);
        if (fin) { s_t[rnk] = tj; cand[rnk] = tj; }
        unsigned m = __ballot_sync(0xFFFFFFFFu, fin);
        if (tid == 0) { s_n1 = __popc(m); atomicAdd(&s_n, __popc(m)); }
    }
    __syncthreads();
    const int n1 = s_n1;

    // ---- phase 2: layer-2 zero crossings, one thread per (segment p, unit k) ----
    if (tid < 21 * 20) {
        int p = tid / 20, k = tid % 20;
        if (p <= n1) {
            float lo = (p == 0)  ? -INFINITY : s_t[p - 1];
            float hi = (p == n1) ?  INFINITY : s_t[p];
            float xr;
            if (n1 == 0)      xr = 0.0f;
            else if (p == 0)  xr = s_t[0] - 1.0f;
            else if (p == n1) xr = s_t[n1 - 1] + 1.0f;
            else              xr = 0.5f * (lo + hi);
            float zs = 0.0f, zi = sb2[k];
            for (int j = 0; j < 20; j++) {
                float pre = fmaf(sa[j], xr, sb1[j]);
                if (pre > 0.0f) {
                    zs = fmaf(sa[j],  sW2[j * 20 + k], zs);
                    zi = fmaf(sb1[j], sW2[j * 20 + k], zi);
                }
            }
            if (zs != 0.0f) {
                float xc = -zi / zs;
                if (isfinite(xc) && xc > lo && xc < hi) {
                    cand[20 + p * 20 + k] = xc;
                    atomicAdd(&s_n, 1);
                }
            }
        }
    }
    __syncthreads();

    // ---- phase 3: bitonic sort of cand[512] ----
    for (int k = 2; k <= 512; k <<= 1) {
        for (int j = k >> 1; j > 0; j >>= 1) {
            int ixj = tid ^ j;
            if (ixj > tid) {
                float a = cand[tid], b = cand[ixj];
                bool dir = ((tid & k) == 0);
                if ((a > b) == dir) { cand[tid] = b; cand[ixj] = a; }
            }
            __syncthreads();
        }
    }

    const int n = s_n;
    if (tid == 0) g_nbp = n;
    g_bp[tid] = cand[tid];                        // +INF padded beyond n

    // ---- phase 4: grid table via range scatter ----
    if (tid <= n) {
        auto cmin = [&](float b) -> int {
            if (!(b > XLO_F)) return 0;
            if (b >= XHI_F)   return NCELL;
            int c = (int)ceilf((b - XLO_F) * INVSTEP_F);
            c = min(max(c, 0), NCELL);
            while (c > 0 && XLO_F + (float)(c - 1) * STEP_F >= b) c--;
            while (c < NCELL && XLO_F + (float)c * STEP_F < b)    c++;
            return c;
        };
        int start = (tid == 0) ? 0     : cmin(cand[tid - 1]);
        int end   = (tid == n) ? NCELL : cmin(cand[tid]);
        for (int c = start; c < end; c++) g_cell[c] = (unsigned short)tid;
    }

    // ---- phase 5: per-segment records, scaled by 1/64 ----
    if (tid <= n) {
        float xr;
        if (n == 0)        xr = 0.0f;
        else if (tid == 0) xr = cand[0] - 1.0f;
        else if (tid == n) xr = cand[n - 1] + 1.0f;
        else               xr = 0.5f * (cand[tid - 1] + cand[tid]);

        float ha[20], hb[20];
        #pragma unroll
        for (int j = 0; j < 20; j++) {
            float pre = fmaf(sa[j], xr, sb1[j]);
            bool act = pre > 0.0f;
            ha[j] = act ? sa[j]  : 0.0f;
            hb[j] = act ? sb1[j] : 0.0f;
        }
        float sm[5] = {0, 0, 0, 0, 0}, cm[5] = {0, 0, 0, 0, 0};
        for (int k = 0; k < 20; k++) {
            float zs = 0.0f, zi = sb2[k];
            #pragma unroll
            for (int j = 0; j < 20; j++) {
                zs = fmaf(ha[j], sW2[j * 20 + k], zs);
                zi = fmaf(hb[j], sW2[j * 20 + k], zi);
            }
            if (fmaf(zs, xr, zi) > 0.0f) {
                #pragma unroll
                for (int m = 0; m < 5; m++) {
                    sm[m] = fmaf(zs, sW3[k * 5 + m], sm[m]);
                    cm[m] = fmaf(zi, sW3[k * 5 + m], cm[m]);
                }
            }
        }
        unsigned int* rec = g_rec + tid * 6;
        rec[0] = __float_as_uint(xr);
        #pragma unroll
        for (int m = 0; m < 5; m++) {
            float v = fmaf(sm[m], xr, cm[m] + sb3[m]);   // f_m at xr
            __half2 h = __floats2half2_rn(sm[m] * 0.015625f, v * 0.015625f);
            rec[1 + m] = *(unsigned int*)&h;
        }
    }
}

// ----------------------------------------------------------------------------
// Encoder kernel: 1 row/thread, 128 thr/block, 10 blocks/SM.
// ----------------------------------------------------------------------------
__device__ __forceinline__ int pwl_find(float x,
                                        const float* __restrict__ s_bp,
                                        const unsigned short* __restrict__ s_cell)
{
    float fc = fmaf(x, INVSTEP_F, HALFCELLS);
    int c = __float2int_rz(fc);
    c = min(max(c, 0), NCELL - 1);
    int s = s_cell[c];
    if (fc < 0.0f) s = 0;                 // x below grid: walk up from 0
    while (s_bp[s] <= x) ++s;             // +INF padding terminates
    return s;
}

__device__ __forceinline__ void pwl_acc(float x, const uint2* __restrict__ p,
                                        float acc[5])
{
    uint2 r0 = p[0], r1 = p[1], r2 = p[2];
    float dx = x - __uint_as_float(r0.x);
    float2 m0 = __half22float2(*(__half2*)&r0.y);
    float2 m1 = __half22float2(*(__half2*)&r1.x);
    float2 m2 = __half22float2(*(__half2*)&r1.y);
    float2 m3 = __half22float2(*(__half2*)&r2.x);
    float2 m4 = __half22float2(*(__half2*)&r2.y);
    acc[0] += fmaf(m0.x, dx, m0.y);
    acc[1] += fmaf(m1.x, dx, m1.y);
    acc[2] += fmaf(m2.x, dx, m2.y);
    acc[3] += fmaf(m3.x, dx, m3.y);
    acc[4] += fmaf(m4.x, dx, m4.y);
}

__global__ __launch_bounds__(128, 10) void enc_kernel(const float* __restrict__ inv)
{
    __shared__ __align__(16) float          s_bp[NBP_MAX];       // 2 KB
    __shared__ __align__(16) unsigned int   s_rec[NSEG_MAX * 6]; // 12 KB
    __shared__ __align__(16) unsigned short s_cell[NCELL];       // 4 KB

    const int tid = threadIdx.x;

    {
        const uint4* src = (const uint4*)g_rec;
        uint4* dst = (uint4*)s_rec;
        #pragma unroll
        for (int i = tid; i < NSEG_MAX * 6 / 4; i += 128) dst[i] = src[i];
        ((float4*)s_bp)[tid] = ((const float4*)g_bp)[tid];
        const uint4* csrc = (const uint4*)g_cell;
        uint4* cdst = (uint4*)s_cell;
        #pragma unroll
        for (int i = tid; i < NCELL / 8; i += 128) cdst[i] = csrc[i];
    }
    __syncthreads();

    const int r = blockIdx.x * 128 + tid;
    const uint2* rec = (const uint2*)s_rec;

    float acc[5] = {0, 0, 0, 0, 0};
    const float4* p0 = (const float4*)inv + (size_t)r * 16;
    #pragma unroll 4
    for (int i = 0; i < 16; i++) {
        float4 a = p0[i];
        int sA = pwl_find(a.x, s_bp, s_cell);
        int sB = pwl_find(a.y, s_bp, s_cell);
        int sC = pwl_find(a.z, s_bp, s_cell);
        int sD = pwl_find(a.w, s_bp, s_cell);
        pwl_acc(a.x, rec + sA * 3, acc);
        pwl_acc(a.y, rec + sB * 3, acc);
        pwl_acc(a.z, rec + sC * 3, acc);
        pwl_acc(a.w, rec + sD * 3, acc);
    }

    #pragma unroll
    for (int m = 0; m < 5; m++) g_mom[m * BATCH + r] = acc[m];
}

// ----------------------------------------------------------------------------
// Decoder kernel: 13 -> 20 -> 20 -> 4, FFMA-bound.
// ----------------------------------------------------------------------------
__global__ __launch_bounds__(256) void dec_kernel(
    const float* __restrict__ noninv,
    const float* __restrict__ dW1,  const float* __restrict__ db1,
    const float* __restrict__ dW2,  const float* __restrict__ db2,
    const float* __restrict__ dW3,  const float* __restrict__ db3,
    float* __restrict__ out)
{
    __shared__ __align__(16) float s_dw[784];
    const int tid = threadIdx.x;

    for (int i = tid; i < 260; i += 256) s_dw[i] = dW1[i];
    if (tid < 20) s_dw[260 + tid] = db1[tid];
    for (int i = tid; i < 400; i += 256) s_dw[280 + i] = dW2[i];
    if (tid < 20) s_dw[680 + tid] = db2[tid];
    if (tid < 80) s_dw[700 + tid] = dW3[tid];
    if (tid < 4)  s_dw[780 + tid] = db3[tid];
    __syncthreads();

    const int r = blockIdx.x * 256 + tid;

    float cat[13];
    #pragma unroll
    for (int m = 0; m < 5; m++) cat[m] = g_mom[m * BATCH + r];
    {
        float4 u0 = *(const float4*)(noninv + (size_t)r * 8);
        float4 u1 = *(const float4*)(noninv + (size_t)r * 8 + 4);
        cat[5] = u0.x; cat[6] = u0.y; cat[7]  = u0.z; cat[8]  = u0.w;
        cat[9] = u1.x; cat[10] = u1.y; cat[11] = u1.z; cat[12] = u1.w;
    }

    float h[20];
    #pragma unroll
    for (int kg = 0; kg < 20; kg += 4) {
        float4 z = *(const float4*)&s_dw[260 + kg];
        #pragma unroll
        for (int c = 0; c < 13; c++) {
            float4 w = *(const float4*)&s_dw[c * 20 + kg];
            z.x = fmaf(cat[c], w.x, z.x);
            z.y = fmaf(cat[c], w.y, z.y);
            z.z = fmaf(cat[c], w.z, z.z);
            z.w = fmaf(cat[c], w.w, z.w);
        }
        h[kg] = fmaxf(z.x, 0.0f); h[kg + 1] = fmaxf(z.y, 0.0f);
        h[kg + 2] = fmaxf(z.z, 0.0f); h[kg + 3] = fmaxf(z.w, 0.0f);
    }

    float g[20];
    #pragma unroll
    for (int kg = 0; kg < 20; kg += 4) {
        float4 z = *(const float4*)&s_dw[680 + kg];
        #pragma unroll
        for (int j = 0; j < 20; j++) {
            float4 w = *(const float4*)&s_dw[280 + j * 20 + kg];
            z.x = fmaf(h[j], w.x, z.x);
            z.y = fmaf(h[j], w.y, z.y);
            z.z = fmaf(h[j], w.z, z.z);
            z.w = fmaf(h[j], w.w, z.w);
        }
        g[kg] = fmaxf(z.x, 0.0f); g[kg + 1] = fmaxf(z.y, 0.0f);
        g[kg + 2] = fmaxf(z.z, 0.0f); g[kg + 3] = fmaxf(z.w, 0.0f);
    }

    float4 o = *(const float4*)&s_dw[780];
    #pragma unroll
    for (int k = 0; k < 20; k++) {
        float4 w = *(const float4*)&s_dw[700 + k * 4];
        o.x = fmaf(g[k], w.x, o.x);
        o.y = fmaf(g[k], w.y, o.y);
        o.z = fmaf(g[k], w.z, o.z);
        o.w = fmaf(g[k], w.w, o.w);
    }
    *(float4*)(out + (size_t)r * 4) = o;
}

// ----------------------------------------------------------------------------
extern "C" void kernel_launch(void* const* d_in, const int* in_sizes, int n_in,
                              void* d_out, int out_size)
{
    (void)in_sizes; (void)n_in; (void)out_size;
    const float* invar  = (const float*)d_in[0];
    const float* noninv = (const float*)d_in[1];
    const float* eW1 = (const float*)d_in[2];
    const float* eb1 = (const float*)d_in[3];
    const float* eW2 = (const float*)d_in[4];
    const float* eb2 = (const float*)d_in[5];
    const float* eW3 = (const float*)d_in[6];
    const float* eb3 = (const float*)d_in[7];
    const float* dW1 = (const float*)d_in[8];
    const float* db1 = (const float*)d_in[9];
    const float* dW2 = (const float*)d_in[10];
    const float* db2 = (const float*)d_in[11];
    const float* dW3 = (const float*)d_in[12];
    const float* db3 = (const float*)d_in[13];

    prep_kernel<<<1, 512>>>(eW1, eb1, eW2, eb2, eW3, eb3);
    enc_kernel<<<BATCH / 128, 128>>>(invar);
    dec_kernel<<<BATCH / 256, 256>>>(noninv, dW1, db1, dW2, db2, dW3, db3,
                                     (float*)d_out);
}